// round 6
// baseline (speedup 1.0000x reference)
#include <cuda_runtime.h>
#include <cuda_bf16.h>
#include <cstdint>

#define N_NODES 50000
#define N_EDGES 800000
#define DIM     128
#define N_GRAPHS 64
#define N_CLASS  10
#define HID      64
#define SCAN_BLOCKS 196   // ceil(50000/256)
#define N_TILES 391       // ceil(50000/128)
#define SA      136       // padded K-stride in smem (bank-conflict-free fragments)

// ---------------- device scratch ----------------
__device__ float g_h[2][N_NODES * DIM];
__device__ unsigned short g_Whi[6 * DIM * DIM]; // row-major W^T [N][K] bf16 hi
__device__ unsigned short g_Wlo[6 * DIM * DIM];
__device__ float g_ns[N_NODES];
__device__ float g_nd[N_NODES];
__device__ int   g_indeg[N_NODES];
__device__ int   g_outdeg[N_NODES];
__device__ int   g_rowptr[N_NODES + 1];
__device__ int   g_cursor[N_NODES];
__device__ int   g_csrsrc[N_EDGES];
__device__ float g_pooled[N_GRAPHS * DIM];
__device__ int   g_gcount[N_GRAPHS];
__device__ int   g_blksum[256];
__device__ int   g_blkoff[256];

__device__ __forceinline__ void split_bf(float x, unsigned short& hi, unsigned short& lo) {
    __nv_bfloat16 h = __float2bfloat16_rn(x);
    hi = __bfloat16_as_ushort(h);
    lo = __bfloat16_as_ushort(__float2bfloat16_rn(x - __bfloat162float(h)));
}

__device__ __forceinline__ void mma16816(float* c, const uint32_t* a, const uint32_t* b) {
    asm volatile(
        "mma.sync.aligned.m16n8k16.row.col.f32.bf16.bf16.f32 "
        "{%0,%1,%2,%3}, {%4,%5,%6,%7}, {%8,%9}, {%0,%1,%2,%3};"
        : "+f"(c[0]), "+f"(c[1]), "+f"(c[2]), "+f"(c[3])
        : "r"(a[0]), "r"(a[1]), "r"(a[2]), "r"(a[3]), "r"(b[0]), "r"(b[1]));
}

// ---------------- init ----------------
__global__ void zero_kernel() {
    int i = blockIdx.x * blockDim.x + threadIdx.x;
    if (i < N_NODES) { g_indeg[i] = 0; g_outdeg[i] = 0; g_cursor[i] = 0; }
    if (i < N_GRAPHS * DIM) g_pooled[i] = 0.0f;
    if (i < N_GRAPHS) g_gcount[i] = 0;
}

__global__ void degree_kernel(const int* __restrict__ src, const int* __restrict__ dst) {
    int e = blockIdx.x * blockDim.x + threadIdx.x;
    if (e < N_EDGES) {
        atomicAdd(&g_outdeg[src[e]], 1);
        atomicAdd(&g_indeg[dst[e]], 1);
    }
}

__global__ void norm_kernel() {
    int i = blockIdx.x * blockDim.x + threadIdx.x;
    if (i < N_NODES) {
        g_ns[i] = rsqrtf((float)max(g_outdeg[i], 1));
        g_nd[i] = rsqrtf((float)max(g_indeg[i], 1));
    }
}

// ---------------- 3-phase parallel scan of g_indeg -> g_rowptr ----------------
__global__ void scan_part1() {
    int i = blockIdx.x * 256 + threadIdx.x;
    int v = (i < N_NODES) ? g_indeg[i] : 0;
#pragma unroll
    for (int o = 16; o; o >>= 1) v += __shfl_down_sync(0xffffffffu, v, o);
    __shared__ int ws[8];
    if ((threadIdx.x & 31) == 0) ws[threadIdx.x >> 5] = v;
    __syncthreads();
    if (threadIdx.x < 8) {
        int s = ws[threadIdx.x];
#pragma unroll
        for (int o = 4; o; o >>= 1) s += __shfl_down_sync(0xffu, s, o);
        if (threadIdx.x == 0) g_blksum[blockIdx.x] = s;
    }
}

__global__ void scan_part2() {
    __shared__ int s[256];
    int t = threadIdx.x;
    int v = (t < SCAN_BLOCKS) ? g_blksum[t] : 0;
    s[t] = v;
    __syncthreads();
    for (int o = 1; o < 256; o <<= 1) {
        int x = (t >= o) ? s[t - o] : 0;
        __syncthreads();
        s[t] += x;
        __syncthreads();
    }
    if (t < SCAN_BLOCKS) g_blkoff[t] = s[t] - v;
}

__global__ void scan_part3() {
    __shared__ int s[256];
    int t = threadIdx.x;
    int i = blockIdx.x * 256 + t;
    int v = (i < N_NODES) ? g_indeg[i] : 0;
    s[t] = v;
    __syncthreads();
    for (int o = 1; o < 256; o <<= 1) {
        int x = (t >= o) ? s[t - o] : 0;
        __syncthreads();
        s[t] += x;
        __syncthreads();
    }
    if (i < N_NODES) {
        int r = g_blkoff[blockIdx.x] + s[t] - v;
        g_rowptr[i] = r;
        if (i == N_NODES - 1) g_rowptr[N_NODES] = r + v;
    }
}

__global__ void fill_csr(const int* __restrict__ src, const int* __restrict__ dst) {
    int e = blockIdx.x * blockDim.x + threadIdx.x;
    if (e < N_EDGES) {
        int v = dst[e];
        int ofs = atomicAdd(&g_cursor[v], 1);
        g_csrsrc[g_rowptr[v] + ofs] = src[e];
    }
}

// ---------------- weight conversion: W [K][N] -> W^T [N][K] bf16 hi/lo ----------------
__global__ void wconvert(const float* W0, const float* W1, const float* W2,
                         const float* W3, const float* W4, const float* W5) {
    int idx = blockIdx.x * 256 + threadIdx.x;
    if (idx >= 6 * DIM * DIM) return;
    int layer = idx >> 14;
    int r = idx & 16383;
    int n = r >> 7, k = r & 127;
    const float* Ws[6] = {W0, W1, W2, W3, W4, W5};
    float val = Ws[layer][k * DIM + n];
    unsigned short hi, lo;
    split_bf(val, hi, lo);
    g_Whi[idx] = hi;   // layer*16384 + n*128 + k
    g_Wlo[idx] = lo;
}

// ---------------- FUSED layer: gather -> smem bf16 split -> mma -> relu/bias/ns -> g_h ----------------
// CTA = 128 dst rows. 512 threads = 16 warps: gather 8 nodes/warp, then 4Mx4N MMA.
template <int SRC_NORM>
__global__ void __launch_bounds__(512, 1) fused_layer(
    const float* __restrict__ ext_in, int in_sel,
    const float* __restrict__ bias, int layer, int out_buf, int do_ps) {
    extern __shared__ __align__(16) unsigned short sm[];
    unsigned short* sAh = sm;
    unsigned short* sAl = sm + 128 * SA;
    unsigned short* sWh = sm + 2 * 128 * SA;
    unsigned short* sWl = sm + 3 * 128 * SA;

    const float* hin = (in_sel == 0) ? g_h[0] : (in_sel == 1) ? g_h[1] : ext_in;
    int tid = threadIdx.x;
    int warp = tid >> 5, lane = tid & 31;

    // stage W tiles (2048 uint4 hi + 2048 lo)
    const uint4* gWh = (const uint4*)(g_Whi + (size_t)layer * (DIM * DIM));
    const uint4* gWl = (const uint4*)(g_Wlo + (size_t)layer * (DIM * DIM));
#pragma unroll
    for (int it = 0; it < 4; it++) {
        int i = tid + it * 512;
        int r = i >> 4, c = (i & 15) << 3;
        *(uint4*)&sWh[r * SA + c] = gWh[i];
        *(uint4*)&sWl[r * SA + c] = gWl[i];
    }

    // gather phase: warp handles rows warp*8 .. warp*8+7 of this tile
    const float4* h4 = (const float4*)hin;
    for (int j = 0; j < 8; j++) {
        int row = warp * 8 + j;
        int v = blockIdx.x * 128 + row;
        float4 acc = make_float4(0.f, 0.f, 0.f, 0.f);
        if (v < N_NODES) {
            int beg = g_rowptr[v];
            int end = g_rowptr[v + 1];
            int i = beg;
            for (; i + 4 <= end; i += 4) {
                int s0 = g_csrsrc[i + 0];
                int s1 = g_csrsrc[i + 1];
                int s2 = g_csrsrc[i + 2];
                int s3 = g_csrsrc[i + 3];
                float w0 = SRC_NORM ? g_ns[s0] : 1.0f;
                float w1 = SRC_NORM ? g_ns[s1] : 1.0f;
                float w2 = SRC_NORM ? g_ns[s2] : 1.0f;
                float w3 = SRC_NORM ? g_ns[s3] : 1.0f;
                float4 v0 = h4[s0 * 32 + lane];
                float4 v1 = h4[s1 * 32 + lane];
                float4 v2 = h4[s2 * 32 + lane];
                float4 v3 = h4[s3 * 32 + lane];
                acc.x += w0 * v0.x; acc.y += w0 * v0.y; acc.z += w0 * v0.z; acc.w += w0 * v0.w;
                acc.x += w1 * v1.x; acc.y += w1 * v1.y; acc.z += w1 * v1.z; acc.w += w1 * v1.w;
                acc.x += w2 * v2.x; acc.y += w2 * v2.y; acc.z += w2 * v2.z; acc.w += w2 * v2.w;
                acc.x += w3 * v3.x; acc.y += w3 * v3.y; acc.z += w3 * v3.z; acc.w += w3 * v3.w;
            }
            for (; i < end; i++) {
                int s = g_csrsrc[i];
                float w = SRC_NORM ? g_ns[s] : 1.0f;
                float4 vv = h4[s * 32 + lane];
                acc.x += w * vv.x; acc.y += w * vv.y; acc.z += w * vv.z; acc.w += w * vv.w;
            }
            float sc = g_nd[v];
            acc.x *= sc; acc.y *= sc; acc.z *= sc; acc.w *= sc;
        }
        unsigned short h0, h1, h2, h3, l0, l1, l2, l3;
        split_bf(acc.x, h0, l0); split_bf(acc.y, h1, l1);
        split_bf(acc.z, h2, l2); split_bf(acc.w, h3, l3);
        *(uint2*)&sAh[row * SA + lane * 4] =
            make_uint2((uint32_t)h0 | ((uint32_t)h1 << 16), (uint32_t)h2 | ((uint32_t)h3 << 16));
        *(uint2*)&sAl[row * SA + lane * 4] =
            make_uint2((uint32_t)l0 | ((uint32_t)l1 << 16), (uint32_t)l2 | ((uint32_t)l3 << 16));
    }
    __syncthreads();

    // MMA phase: 16 warps = 4M x 4N, warp tile 32x32
    int wm = warp & 3, wn = warp >> 2;
    int bm = wm * 32, bn = wn * 32;
    int lr = lane >> 2, lc = (lane & 3) * 2;

    float acc[2][4][4];
#pragma unroll
    for (int mi = 0; mi < 2; mi++)
#pragma unroll
        for (int ni = 0; ni < 4; ni++)
#pragma unroll
            for (int q = 0; q < 4; q++) acc[mi][ni][q] = 0.f;

    const unsigned short* AP[3] = {sAh, sAh, sAl};
    const unsigned short* BP[3] = {sWh, sWl, sWh};

#pragma unroll
    for (int p = 0; p < 3; p++) {
        const unsigned short* A = AP[p];
        const unsigned short* B = BP[p];
#pragma unroll
        for (int k = 0; k < 8; k++) {
            int k0 = k * 16;
            uint32_t af[2][4], bf[4][2];
#pragma unroll
            for (int mi = 0; mi < 2; mi++) {
                int r = bm + mi * 16 + lr;
                af[mi][0] = *(const uint32_t*)&A[r * SA + k0 + lc];
                af[mi][1] = *(const uint32_t*)&A[(r + 8) * SA + k0 + lc];
                af[mi][2] = *(const uint32_t*)&A[r * SA + k0 + 8 + lc];
                af[mi][3] = *(const uint32_t*)&A[(r + 8) * SA + k0 + 8 + lc];
            }
#pragma unroll
            for (int ni = 0; ni < 4; ni++) {
                int cc = bn + ni * 8 + lr;
                bf[ni][0] = *(const uint32_t*)&B[cc * SA + k0 + lc];
                bf[ni][1] = *(const uint32_t*)&B[cc * SA + k0 + 8 + lc];
            }
#pragma unroll
            for (int mi = 0; mi < 2; mi++)
#pragma unroll
                for (int ni = 0; ni < 4; ni++)
                    mma16816(acc[mi][ni], af[mi], bf[ni]);
        }
    }

    float* C = g_h[out_buf];
#pragma unroll
    for (int mi = 0; mi < 2; mi++) {
        int r0 = blockIdx.x * 128 + bm + mi * 16 + lr;
        int r1 = r0 + 8;
        float ps0 = 1.f, ps1 = 1.f;
        if (do_ps) {
            if (r0 < N_NODES) ps0 = g_ns[r0];
            if (r1 < N_NODES) ps1 = g_ns[r1];
        }
#pragma unroll
        for (int ni = 0; ni < 4; ni++) {
            int col = bn + ni * 8 + lc;
            float2 bv = *(const float2*)&bias[col];
            if (r0 < N_NODES) {
                float2 o;
                o.x = fmaxf(acc[mi][ni][0] + bv.x, 0.f) * ps0;
                o.y = fmaxf(acc[mi][ni][1] + bv.y, 0.f) * ps0;
                *(float2*)&C[(size_t)r0 * DIM + col] = o;
            }
            if (r1 < N_NODES) {
                float2 o;
                o.x = fmaxf(acc[mi][ni][2] + bv.x, 0.f) * ps1;
                o.y = fmaxf(acc[mi][ni][3] + bv.y, 0.f) * ps1;
                *(float2*)&C[(size_t)r1 * DIM + col] = o;
            }
        }
    }
}

// ---------------- final aggregation (fp32 exact, no norm) for h_agg ----------------
__global__ void aggregate_final(int in_sel, float* __restrict__ out) {
    const float* hin = g_h[in_sel];
    int v = (blockIdx.x * blockDim.x + threadIdx.x) >> 5;
    if (v >= N_NODES) return;
    int lane = threadIdx.x & 31;

    int beg = g_rowptr[v];
    int end = g_rowptr[v + 1];

    const float4* h4 = (const float4*)hin;
    float4 acc = make_float4(0.f, 0.f, 0.f, 0.f);

    int i = beg;
    for (; i + 4 <= end; i += 4) {
        int s0 = g_csrsrc[i + 0];
        int s1 = g_csrsrc[i + 1];
        int s2 = g_csrsrc[i + 2];
        int s3 = g_csrsrc[i + 3];
        float4 v0 = h4[s0 * 32 + lane];
        float4 v1 = h4[s1 * 32 + lane];
        float4 v2 = h4[s2 * 32 + lane];
        float4 v3 = h4[s3 * 32 + lane];
        acc.x += v0.x + v1.x + v2.x + v3.x;
        acc.y += v0.y + v1.y + v2.y + v3.y;
        acc.z += v0.z + v1.z + v2.z + v3.z;
        acc.w += v0.w + v1.w + v2.w + v3.w;
    }
    for (; i < end; i++) {
        int s = g_csrsrc[i];
        float4 vv = h4[s * 32 + lane];
        acc.x += vv.x; acc.y += vv.y; acc.z += vv.z; acc.w += vv.w;
    }
    ((float4*)out)[v * 32 + lane] = acc;
}

// ---------------- pooling: sorted graph_id -> register accumulation ----------------
__global__ void pool_kernel(int buf, const int* __restrict__ gid) {
    const float* h = g_h[buf];
    int group = blockIdx.x * 2 + (threadIdx.x >> 7);
    int d = threadIdx.x & 127;
    int start = group * 128;
    if (start >= N_NODES) return;
    int end = min(start + 128, N_NODES);

    int cur = gid[start];
    float acc = 0.f;
    int cnt = 0;
    for (int n = start; n < end; n++) {
        int g = gid[n];
        if (g != cur) {
            atomicAdd(&g_pooled[cur * DIM + d], acc);
            if (d == 0) atomicAdd(&g_gcount[cur], cnt);
            acc = 0.f; cnt = 0; cur = g;
        }
        acc += h[n * DIM + d];
        cnt++;
    }
    atomicAdd(&g_pooled[cur * DIM + d], acc);
    if (d == 0) atomicAdd(&g_gcount[cur], cnt);
}

// ---------------- head MLP ----------------
__global__ void mlp_kernel(const float* __restrict__ Wa, const float* __restrict__ ba,
                           const float* __restrict__ Wb, const float* __restrict__ bb,
                           float* __restrict__ out) {
    __shared__ float pm[N_GRAPHS * DIM];
    __shared__ float z[N_GRAPHS * HID];
    int t = threadIdx.x;

    for (int i = t; i < N_GRAPHS * DIM; i += 256) {
        int g = i / DIM;
        float cnt = fmaxf((float)g_gcount[g], 1.0f);
        pm[i] = g_pooled[i] / cnt;
    }
    __syncthreads();

    for (int i = t; i < N_GRAPHS * HID; i += 256) {
        int g = i / HID, j = i % HID;
        float s = ba[j];
        for (int d = 0; d < DIM; d++) s += pm[g * DIM + d] * Wa[d * HID + j];
        z[i] = fmaxf(s, 0.0f);
    }
    __syncthreads();

    for (int i = t; i < N_GRAPHS * N_CLASS; i += 256) {
        int g = i / N_CLASS, c = i % N_CLASS;
        float s = bb[c];
        for (int j = 0; j < HID; j++) s += z[g * HID + j] * Wb[j * N_CLASS + c];
        out[i] = s;
    }
}

// ---------------- launch ----------------
extern "C" void kernel_launch(void* const* d_in, const int* in_sizes, int n_in,
                              void* d_out, int out_size) {
    const float* feat = (const float*)d_in[0];
    const int* src = (const int*)d_in[1];
    const int* dst = (const int*)d_in[2];
    const int* gid = (const int*)d_in[3];
    const float* Ws[6] = {(const float*)d_in[4], (const float*)d_in[6], (const float*)d_in[8],
                          (const float*)d_in[10], (const float*)d_in[12], (const float*)d_in[14]};
    const float* bs[6] = {(const float*)d_in[5], (const float*)d_in[7], (const float*)d_in[9],
                          (const float*)d_in[11], (const float*)d_in[13], (const float*)d_in[15]};
    const float* Wa = (const float*)d_in[16];
    const float* ba = (const float*)d_in[17];
    const float* Wb = (const float*)d_in[18];
    const float* bb = (const float*)d_in[19];
    float* out = (float*)d_out;

    const int SMEM_DYN = 4 * 128 * SA * 2;   // 139264 B
    cudaFuncSetAttribute(fused_layer<1>, cudaFuncAttributeMaxDynamicSharedMemorySize, SMEM_DYN);
    cudaFuncSetAttribute(fused_layer<0>, cudaFuncAttributeMaxDynamicSharedMemorySize, SMEM_DYN);

    // graph structure
    zero_kernel<<<SCAN_BLOCKS, 256>>>();
    degree_kernel<<<(N_EDGES + 255) / 256, 256>>>(src, dst);
    norm_kernel<<<SCAN_BLOCKS, 256>>>();
    scan_part1<<<SCAN_BLOCKS, 256>>>();
    scan_part2<<<1, 256>>>();
    scan_part3<<<SCAN_BLOCKS, 256>>>();
    fill_csr<<<(N_EDGES + 255) / 256, 256>>>(src, dst);
    wconvert<<<(6 * DIM * DIM + 255) / 256, 256>>>(Ws[0], Ws[1], Ws[2], Ws[3], Ws[4], Ws[5]);

    // Layer 0: per-edge src norm. GEMM epilogue pre-scales layers 0..4 by ns,
    // so layers 1..5 gather without per-edge norm loads. relu(x)*ns == relu(x*ns).
    fused_layer<1><<<N_TILES, 512, SMEM_DYN>>>(feat, -1, bs[0], 0, 0, 1);
    for (int L = 1; L < 6; L++) {
        fused_layer<0><<<N_TILES, 512, SMEM_DYN>>>(nullptr, (L - 1) & 1, bs[L], L, L & 1, (L < 5) ? 1 : 0);
    }
    // final features in g_h[1]

    pool_kernel<<<SCAN_BLOCKS, 256>>>(1, gid);
    mlp_kernel<<<1, 256>>>(Wa, ba, Wb, bb, out);

    // unnormalized aggregation h_agg [50000,128] (fp32 exact)
    aggregate_final<<<(N_NODES * 32 + 255) / 256, 256>>>(1, out + N_GRAPHS * N_CLASS);
}

// round 7
// speedup vs baseline: 1.2265x; 1.2265x over previous
#include <cuda_runtime.h>
#include <cuda_bf16.h>
#include <cstdint>

#define N_NODES 50000
#define N_EDGES 800000
#define DIM     128
#define N_GRAPHS 64
#define N_CLASS  10
#define HID      64
#define SCAN_BLOCKS 196   // ceil(50000/256)
#define N_TILES 391       // ceil(50000/128)
#define N_PAD   (N_TILES * 128)
#define GTILES  782       // N_PAD / 64
#define SA      136       // padded K-stride in smem (bank-conflict-free fragments)

// ---------------- device scratch ----------------
__device__ float g_h[2][N_NODES * DIM];
__device__ unsigned short g_Ahi[N_PAD * DIM];   // row-major bf16 hi of aggregated feats
__device__ unsigned short g_Alo[N_PAD * DIM];   // row-major bf16 lo
__device__ unsigned short g_Whi[6 * DIM * DIM]; // row-major W^T [N][K] bf16 hi
__device__ unsigned short g_Wlo[6 * DIM * DIM];
__device__ float g_ns[N_NODES];
__device__ float g_nd[N_NODES];
__device__ int   g_indeg[N_NODES];
__device__ int   g_outdeg[N_NODES];
__device__ int   g_rowptr[N_NODES + 1];
__device__ int   g_cursor[N_NODES];
__device__ int   g_csrsrc[N_EDGES];
__device__ float g_pooled[N_GRAPHS * DIM];
__device__ int   g_gcount[N_GRAPHS];
__device__ int   g_blksum[256];
__device__ int   g_blkoff[256];

__device__ __forceinline__ void split_bf(float x, unsigned short& hi, unsigned short& lo) {
    __nv_bfloat16 h = __float2bfloat16_rn(x);
    hi = __bfloat16_as_ushort(h);
    lo = __bfloat16_as_ushort(__float2bfloat16_rn(x - __bfloat162float(h)));
}

__device__ __forceinline__ void mma16816(float* c, const uint32_t* a, const uint32_t* b) {
    asm volatile(
        "mma.sync.aligned.m16n8k16.row.col.f32.bf16.bf16.f32 "
        "{%0,%1,%2,%3}, {%4,%5,%6,%7}, {%8,%9}, {%0,%1,%2,%3};"
        : "+f"(c[0]), "+f"(c[1]), "+f"(c[2]), "+f"(c[3])
        : "r"(a[0]), "r"(a[1]), "r"(a[2]), "r"(a[3]), "r"(b[0]), "r"(b[1]));
}

// ---------------- init ----------------
__global__ void zero_kernel() {
    int i = blockIdx.x * blockDim.x + threadIdx.x;
    if (i < N_NODES) { g_indeg[i] = 0; g_outdeg[i] = 0; g_cursor[i] = 0; }
    if (i < N_GRAPHS * DIM) g_pooled[i] = 0.0f;
    if (i < N_GRAPHS) g_gcount[i] = 0;
    // zero padded tail rows (50000..50047) once; they never get written again
    if (i < 768) ((uint4*)(g_Ahi + N_NODES * DIM))[i] = make_uint4(0, 0, 0, 0);
    else if (i < 1536) ((uint4*)(g_Alo + N_NODES * DIM))[i - 768] = make_uint4(0, 0, 0, 0);
}

__global__ void degree_kernel(const int* __restrict__ src, const int* __restrict__ dst) {
    int e = blockIdx.x * blockDim.x + threadIdx.x;
    if (e < N_EDGES) {
        atomicAdd(&g_outdeg[src[e]], 1);
        atomicAdd(&g_indeg[dst[e]], 1);
    }
}

__global__ void norm_kernel() {
    int i = blockIdx.x * blockDim.x + threadIdx.x;
    if (i < N_NODES) {
        g_ns[i] = rsqrtf((float)max(g_outdeg[i], 1));
        g_nd[i] = rsqrtf((float)max(g_indeg[i], 1));
    }
}

// ---------------- 3-phase parallel scan of g_indeg -> g_rowptr ----------------
__global__ void scan_part1() {
    int i = blockIdx.x * 256 + threadIdx.x;
    int v = (i < N_NODES) ? g_indeg[i] : 0;
#pragma unroll
    for (int o = 16; o; o >>= 1) v += __shfl_down_sync(0xffffffffu, v, o);
    __shared__ int ws[8];
    if ((threadIdx.x & 31) == 0) ws[threadIdx.x >> 5] = v;
    __syncthreads();
    if (threadIdx.x < 8) {
        int s = ws[threadIdx.x];
#pragma unroll
        for (int o = 4; o; o >>= 1) s += __shfl_down_sync(0xffu, s, o);
        if (threadIdx.x == 0) g_blksum[blockIdx.x] = s;
    }
}

__global__ void scan_part2() {
    __shared__ int s[256];
    int t = threadIdx.x;
    int v = (t < SCAN_BLOCKS) ? g_blksum[t] : 0;
    s[t] = v;
    __syncthreads();
    for (int o = 1; o < 256; o <<= 1) {
        int x = (t >= o) ? s[t - o] : 0;
        __syncthreads();
        s[t] += x;
        __syncthreads();
    }
    if (t < SCAN_BLOCKS) g_blkoff[t] = s[t] - v;
}

__global__ void scan_part3() {
    __shared__ int s[256];
    int t = threadIdx.x;
    int i = blockIdx.x * 256 + t;
    int v = (i < N_NODES) ? g_indeg[i] : 0;
    s[t] = v;
    __syncthreads();
    for (int o = 1; o < 256; o <<= 1) {
        int x = (t >= o) ? s[t - o] : 0;
        __syncthreads();
        s[t] += x;
        __syncthreads();
    }
    if (i < N_NODES) {
        int r = g_blkoff[blockIdx.x] + s[t] - v;
        g_rowptr[i] = r;
        if (i == N_NODES - 1) g_rowptr[N_NODES] = r + v;
    }
}

__global__ void fill_csr(const int* __restrict__ src, const int* __restrict__ dst) {
    int e = blockIdx.x * blockDim.x + threadIdx.x;
    if (e < N_EDGES) {
        int v = dst[e];
        int ofs = atomicAdd(&g_cursor[v], 1);
        g_csrsrc[g_rowptr[v] + ofs] = src[e];
    }
}

// ---------------- weight conversion: W [K][N] -> W^T [N][K] bf16 hi/lo ----------------
__global__ void wconvert(const float* W0, const float* W1, const float* W2,
                         const float* W3, const float* W4, const float* W5) {
    int idx = blockIdx.x * 256 + threadIdx.x;
    if (idx >= 6 * DIM * DIM) return;
    int layer = idx >> 14;
    int r = idx & 16383;
    int n = r >> 7, k = r & 127;
    const float* Ws[6] = {W0, W1, W2, W3, W4, W5};
    float val = Ws[layer][k * DIM + n];
    unsigned short hi, lo;
    split_bf(val, hi, lo);
    g_Whi[idx] = hi;   // layer*16384 + n*128 + k
    g_Wlo[idx] = lo;
}

// ---------------- aggregation: one warp per destination node, 4x unrolled ----------------
// OUT_BF16=1: write bf16 hi/lo row-major (GEMM input). Else fp32 to ext_out.
template <int SRC_NORM, int DST_NORM, int OUT_BF16>
__global__ void aggregate_kernel(const float* __restrict__ ext_in, int in_sel,
                                 float* __restrict__ ext_out) {
    const float* hin = (in_sel == 0) ? g_h[0] : (in_sel == 1) ? g_h[1] : ext_in;

    int v = (blockIdx.x * blockDim.x + threadIdx.x) >> 5;
    if (v >= N_NODES) return;
    int lane = threadIdx.x & 31;

    int beg = g_rowptr[v];
    int end = g_rowptr[v + 1];

    const float4* h4 = (const float4*)hin;
    float4 acc = make_float4(0.f, 0.f, 0.f, 0.f);

    int i = beg;
    for (; i + 4 <= end; i += 4) {
        int s0 = g_csrsrc[i + 0];
        int s1 = g_csrsrc[i + 1];
        int s2 = g_csrsrc[i + 2];
        int s3 = g_csrsrc[i + 3];
        float w0 = SRC_NORM ? g_ns[s0] : 1.0f;
        float w1 = SRC_NORM ? g_ns[s1] : 1.0f;
        float w2 = SRC_NORM ? g_ns[s2] : 1.0f;
        float w3 = SRC_NORM ? g_ns[s3] : 1.0f;
        float4 v0 = h4[s0 * 32 + lane];
        float4 v1 = h4[s1 * 32 + lane];
        float4 v2 = h4[s2 * 32 + lane];
        float4 v3 = h4[s3 * 32 + lane];
        acc.x += w0 * v0.x; acc.y += w0 * v0.y; acc.z += w0 * v0.z; acc.w += w0 * v0.w;
        acc.x += w1 * v1.x; acc.y += w1 * v1.y; acc.z += w1 * v1.z; acc.w += w1 * v1.w;
        acc.x += w2 * v2.x; acc.y += w2 * v2.y; acc.z += w2 * v2.z; acc.w += w2 * v2.w;
        acc.x += w3 * v3.x; acc.y += w3 * v3.y; acc.z += w3 * v3.z; acc.w += w3 * v3.w;
    }
    for (; i < end; i++) {
        int s = g_csrsrc[i];
        float w = SRC_NORM ? g_ns[s] : 1.0f;
        float4 vv = h4[s * 32 + lane];
        acc.x += w * vv.x; acc.y += w * vv.y; acc.z += w * vv.z; acc.w += w * vv.w;
    }
    if (DST_NORM) {
        float sc = g_nd[v];
        acc.x *= sc; acc.y *= sc; acc.z *= sc; acc.w *= sc;
    }

    if (OUT_BF16) {
        unsigned short h0, h1, h2, h3, l0, l1, l2, l3;
        split_bf(acc.x, h0, l0); split_bf(acc.y, h1, l1);
        split_bf(acc.z, h2, l2); split_bf(acc.w, h3, l3);
        uint2 hv = make_uint2((uint32_t)h0 | ((uint32_t)h1 << 16),
                              (uint32_t)h2 | ((uint32_t)h3 << 16));
        uint2 lv = make_uint2((uint32_t)l0 | ((uint32_t)l1 << 16),
                              (uint32_t)l2 | ((uint32_t)l3 << 16));
        *(uint2*)&g_Ahi[(size_t)v * DIM + lane * 4] = hv;
        *(uint2*)&g_Alo[(size_t)v * DIM + lane * 4] = lv;
    } else {
        ((float4*)ext_out)[v * 32 + lane] = acc;
    }
}

// ---------------- tensor-core GEMM via mma.sync (bf16x2 split, 3 passes) ----------------
// 64-row tiles, 104KB smem -> 2 CTAs/SM. 8 warps = 2M x 4N, warp tile 32x32.
__global__ void __launch_bounds__(256, 2) gemm_mma(
    const float* __restrict__ b, int layer, int out_buf, int do_ps) {
    extern __shared__ __align__(16) unsigned short sm[];
    unsigned short* sAh = sm;                    // 64 x SA
    unsigned short* sAl = sm + 64 * SA;          // 64 x SA
    unsigned short* sWh = sm + 128 * SA;         // 128 x SA
    unsigned short* sWl = sm + 256 * SA;         // 128 x SA

    int tid = threadIdx.x;
    const uint4* gAh = (const uint4*)(g_Ahi + (size_t)blockIdx.x * (64 * DIM));
    const uint4* gAl = (const uint4*)(g_Alo + (size_t)blockIdx.x * (64 * DIM));
    const uint4* gWh = (const uint4*)(g_Whi + (size_t)layer * (DIM * DIM));
    const uint4* gWl = (const uint4*)(g_Wlo + (size_t)layer * (DIM * DIM));

    // stage A: 1024 uint4 per buffer (4/thread); W: 2048 uint4 per buffer (8/thread)
#pragma unroll
    for (int it = 0; it < 4; it++) {
        int i = tid + it * 256;
        int r = i >> 4, c = (i & 15) << 3;
        *(uint4*)&sAh[r * SA + c] = gAh[i];
        *(uint4*)&sAl[r * SA + c] = gAl[i];
    }
#pragma unroll
    for (int it = 0; it < 8; it++) {
        int i = tid + it * 256;
        int r = i >> 4, c = (i & 15) << 3;
        *(uint4*)&sWh[r * SA + c] = gWh[i];
        *(uint4*)&sWl[r * SA + c] = gWl[i];
    }
    __syncthreads();

    int warp = tid >> 5, lane = tid & 31;
    int wm = warp & 1, wn = warp >> 1;           // 2 M-warps x 4 N-warps
    int bm = wm * 32, bn = wn * 32;
    int lr = lane >> 2, lc = (lane & 3) * 2;

    float acc[2][4][4];
#pragma unroll
    for (int mi = 0; mi < 2; mi++)
#pragma unroll
        for (int ni = 0; ni < 4; ni++)
#pragma unroll
            for (int q = 0; q < 4; q++) acc[mi][ni][q] = 0.f;

    const unsigned short* AP[3] = {sAh, sAh, sAl};
    const unsigned short* BP[3] = {sWh, sWl, sWh};

#pragma unroll
    for (int p = 0; p < 3; p++) {
        const unsigned short* A = AP[p];
        const unsigned short* B = BP[p];
#pragma unroll
        for (int k = 0; k < 8; k++) {
            int k0 = k * 16;
            uint32_t af[2][4], bf[4][2];
#pragma unroll
            for (int mi = 0; mi < 2; mi++) {
                int r = bm + mi * 16 + lr;
                af[mi][0] = *(const uint32_t*)&A[r * SA + k0 + lc];
                af[mi][1] = *(const uint32_t*)&A[(r + 8) * SA + k0 + lc];
                af[mi][2] = *(const uint32_t*)&A[r * SA + k0 + 8 + lc];
                af[mi][3] = *(const uint32_t*)&A[(r + 8) * SA + k0 + 8 + lc];
            }
#pragma unroll
            for (int ni = 0; ni < 4; ni++) {
                int cc = bn + ni * 8 + lr;
                bf[ni][0] = *(const uint32_t*)&B[cc * SA + k0 + lc];
                bf[ni][1] = *(const uint32_t*)&B[cc * SA + k0 + 8 + lc];
            }
#pragma unroll
            for (int mi = 0; mi < 2; mi++)
#pragma unroll
                for (int ni = 0; ni < 4; ni++)
                    mma16816(acc[mi][ni], af[mi], bf[ni]);
        }
    }

    float* C = g_h[out_buf];
#pragma unroll
    for (int mi = 0; mi < 2; mi++) {
        int r0 = blockIdx.x * 64 + bm + mi * 16 + lr;
        int r1 = r0 + 8;
        float ps0 = 1.f, ps1 = 1.f;
        if (do_ps) {
            if (r0 < N_NODES) ps0 = g_ns[r0];
            if (r1 < N_NODES) ps1 = g_ns[r1];
        }
#pragma unroll
        for (int ni = 0; ni < 4; ni++) {
            int col = bn + ni * 8 + lc;
            float2 bv = *(const float2*)&b[col];
            if (r0 < N_NODES) {
                float2 o;
                o.x = fmaxf(acc[mi][ni][0] + bv.x, 0.f) * ps0;
                o.y = fmaxf(acc[mi][ni][1] + bv.y, 0.f) * ps0;
                *(float2*)&C[(size_t)r0 * DIM + col] = o;
            }
            if (r1 < N_NODES) {
                float2 o;
                o.x = fmaxf(acc[mi][ni][2] + bv.x, 0.f) * ps1;
                o.y = fmaxf(acc[mi][ni][3] + bv.y, 0.f) * ps1;
                *(float2*)&C[(size_t)r1 * DIM + col] = o;
            }
        }
    }
}

// ---------------- pooling: sorted graph_id -> register accumulation ----------------
__global__ void pool_kernel(int buf, const int* __restrict__ gid) {
    const float* h = g_h[buf];
    int group = blockIdx.x * 2 + (threadIdx.x >> 7);
    int d = threadIdx.x & 127;
    int start = group * 128;
    if (start >= N_NODES) return;
    int end = min(start + 128, N_NODES);

    int cur = gid[start];
    float acc = 0.f;
    int cnt = 0;
    for (int n = start; n < end; n++) {
        int g = gid[n];
        if (g != cur) {
            atomicAdd(&g_pooled[cur * DIM + d], acc);
            if (d == 0) atomicAdd(&g_gcount[cur], cnt);
            acc = 0.f; cnt = 0; cur = g;
        }
        acc += h[n * DIM + d];
        cnt++;
    }
    atomicAdd(&g_pooled[cur * DIM + d], acc);
    if (d == 0) atomicAdd(&g_gcount[cur], cnt);
}

// ---------------- head MLP ----------------
__global__ void mlp_kernel(const float* __restrict__ Wa, const float* __restrict__ ba,
                           const float* __restrict__ Wb, const float* __restrict__ bb,
                           float* __restrict__ out) {
    __shared__ float pm[N_GRAPHS * DIM];
    __shared__ float z[N_GRAPHS * HID];
    int t = threadIdx.x;

    for (int i = t; i < N_GRAPHS * DIM; i += 256) {
        int g = i / DIM;
        float cnt = fmaxf((float)g_gcount[g], 1.0f);
        pm[i] = g_pooled[i] / cnt;
    }
    __syncthreads();

    for (int i = t; i < N_GRAPHS * HID; i += 256) {
        int g = i / HID, j = i % HID;
        float s = ba[j];
        for (int d = 0; d < DIM; d++) s += pm[g * DIM + d] * Wa[d * HID + j];
        z[i] = fmaxf(s, 0.0f);
    }
    __syncthreads();

    for (int i = t; i < N_GRAPHS * N_CLASS; i += 256) {
        int g = i / N_CLASS, c = i % N_CLASS;
        float s = bb[c];
        for (int j = 0; j < HID; j++) s += z[g * HID + j] * Wb[j * N_CLASS + c];
        out[i] = s;
    }
}

// ---------------- launch ----------------
extern "C" void kernel_launch(void* const* d_in, const int* in_sizes, int n_in,
                              void* d_out, int out_size) {
    const float* feat = (const float*)d_in[0];
    const int* src = (const int*)d_in[1];
    const int* dst = (const int*)d_in[2];
    const int* gid = (const int*)d_in[3];
    const float* Ws[6] = {(const float*)d_in[4], (const float*)d_in[6], (const float*)d_in[8],
                          (const float*)d_in[10], (const float*)d_in[12], (const float*)d_in[14]};
    const float* bs[6] = {(const float*)d_in[5], (const float*)d_in[7], (const float*)d_in[9],
                          (const float*)d_in[11], (const float*)d_in[13], (const float*)d_in[15]};
    const float* Wa = (const float*)d_in[16];
    const float* ba = (const float*)d_in[17];
    const float* Wb = (const float*)d_in[18];
    const float* bb = (const float*)d_in[19];
    float* out = (float*)d_out;

    const int SMEM_DYN = (2 * 64 + 2 * 128) * SA * 2;   // 104448 B -> 2 CTAs/SM
    cudaFuncSetAttribute(gemm_mma, cudaFuncAttributeMaxDynamicSharedMemorySize, SMEM_DYN);

    // graph structure
    zero_kernel<<<SCAN_BLOCKS, 256>>>();
    degree_kernel<<<(N_EDGES + 255) / 256, 256>>>(src, dst);
    norm_kernel<<<SCAN_BLOCKS, 256>>>();
    scan_part1<<<SCAN_BLOCKS, 256>>>();
    scan_part2<<<1, 256>>>();
    scan_part3<<<SCAN_BLOCKS, 256>>>();
    fill_csr<<<(N_EDGES + 255) / 256, 256>>>(src, dst);
    wconvert<<<(6 * DIM * DIM + 255) / 256, 256>>>(Ws[0], Ws[1], Ws[2], Ws[3], Ws[4], Ws[5]);

    const int AGG_GRID = (N_NODES * 32 + 255) / 256;

    // Layer 0: per-edge src norm. GEMM epilogue pre-scales layers 0..4 by ns,
    // so layers 1..5 aggregate without per-edge norm loads. relu(x)*ns == relu(x*ns).
    aggregate_kernel<1, 1, 1><<<AGG_GRID, 256>>>(feat, -1, nullptr);
    gemm_mma<<<GTILES, 256, SMEM_DYN>>>(bs[0], 0, 0, 1);

    for (int L = 1; L < 6; L++) {
        aggregate_kernel<0, 1, 1><<<AGG_GRID, 256>>>(nullptr, (L - 1) & 1, nullptr);
        gemm_mma<<<GTILES, 256, SMEM_DYN>>>(bs[L], L, L & 1, (L < 5) ? 1 : 0);
    }
    // final features in g_h[1]

    pool_kernel<<<SCAN_BLOCKS, 256>>>(1, gid);
    mlp_kernel<<<1, 256>>>(Wa, ba, Wb, bb, out);

    // unnormalized aggregation h_agg [50000,128] (fp32 exact)
    aggregate_kernel<0, 0, 0><<<AGG_GRID, 256>>>(nullptr, 1, out + N_GRAPHS * N_CLASS);
}

// round 8
// speedup vs baseline: 1.3766x; 1.1224x over previous
#include <cuda_runtime.h>
#include <cuda_bf16.h>
#include <cstdint>

#define N_NODES 50000
#define N_EDGES 800000
#define DIM     128
#define N_GRAPHS 64
#define N_CLASS  10
#define HID      64
#define SCAN_BLOCKS 196   // ceil(50000/256)
#define N_TILES 391       // ceil(50000/128)
#define N_PAD   (N_TILES * 128)
#define SA      136       // padded K-stride in smem (bank-conflict-free fragments)

// ---------------- device scratch ----------------
__device__ float g_h[2][N_NODES * DIM];
__device__ unsigned short g_Ahi[N_PAD * DIM];   // row-major bf16 hi of aggregated feats
__device__ unsigned short g_Alo[N_PAD * DIM];   // row-major bf16 lo
__device__ unsigned short g_Whi[6 * DIM * DIM]; // row-major W^T [N][K] bf16 hi
__device__ unsigned short g_Wlo[6 * DIM * DIM];
__device__ float g_ns[N_NODES];
__device__ float g_nd[N_NODES];
__device__ int   g_indeg[N_NODES];
__device__ int   g_outdeg[N_NODES];
__device__ int   g_rowptr[N_NODES + 1];
__device__ int   g_cursor[N_NODES];
__device__ int   g_csrsrc[N_EDGES];
__device__ float g_pooled[N_GRAPHS * DIM];
__device__ int   g_gcount[N_GRAPHS];
__device__ int   g_blksum[256];
__device__ int   g_blkoff[256];

__device__ __forceinline__ void split_bf(float x, unsigned short& hi, unsigned short& lo) {
    __nv_bfloat16 h = __float2bfloat16_rn(x);
    hi = __bfloat16_as_ushort(h);
    lo = __bfloat16_as_ushort(__float2bfloat16_rn(x - __bfloat162float(h)));
}

__device__ __forceinline__ void mma16816(float* c, const uint32_t* a, const uint32_t* b) {
    asm volatile(
        "mma.sync.aligned.m16n8k16.row.col.f32.bf16.bf16.f32 "
        "{%0,%1,%2,%3}, {%4,%5,%6,%7}, {%8,%9}, {%0,%1,%2,%3};"
        : "+f"(c[0]), "+f"(c[1]), "+f"(c[2]), "+f"(c[3])
        : "r"(a[0]), "r"(a[1]), "r"(a[2]), "r"(a[3]), "r"(b[0]), "r"(b[1]));
}

// ---------------- init ----------------
__global__ void zero_kernel() {
    int i = blockIdx.x * blockDim.x + threadIdx.x;
    if (i < N_NODES) { g_indeg[i] = 0; g_outdeg[i] = 0; g_cursor[i] = 0; }
    if (i < N_GRAPHS * DIM) g_pooled[i] = 0.0f;
    if (i < N_GRAPHS) g_gcount[i] = 0;
    // zero padded tail rows (50000..50047) once; they never get written again
    if (i < 768) ((uint4*)(g_Ahi + N_NODES * DIM))[i] = make_uint4(0, 0, 0, 0);
    else if (i < 1536) ((uint4*)(g_Alo + N_NODES * DIM))[i - 768] = make_uint4(0, 0, 0, 0);
}

__global__ void degree_kernel(const int* __restrict__ src, const int* __restrict__ dst) {
    int e = blockIdx.x * blockDim.x + threadIdx.x;
    if (e < N_EDGES) {
        atomicAdd(&g_outdeg[src[e]], 1);
        atomicAdd(&g_indeg[dst[e]], 1);
    }
}

__global__ void norm_kernel() {
    int i = blockIdx.x * blockDim.x + threadIdx.x;
    if (i < N_NODES) {
        g_ns[i] = rsqrtf((float)max(g_outdeg[i], 1));
        g_nd[i] = rsqrtf((float)max(g_indeg[i], 1));
    }
}

// ---------------- 3-phase parallel scan of g_indeg -> g_rowptr ----------------
__global__ void scan_part1() {
    int i = blockIdx.x * 256 + threadIdx.x;
    int v = (i < N_NODES) ? g_indeg[i] : 0;
#pragma unroll
    for (int o = 16; o; o >>= 1) v += __shfl_down_sync(0xffffffffu, v, o);
    __shared__ int ws[8];
    if ((threadIdx.x & 31) == 0) ws[threadIdx.x >> 5] = v;
    __syncthreads();
    if (threadIdx.x < 8) {
        int s = ws[threadIdx.x];
#pragma unroll
        for (int o = 4; o; o >>= 1) s += __shfl_down_sync(0xffu, s, o);
        if (threadIdx.x == 0) g_blksum[blockIdx.x] = s;
    }
}

__global__ void scan_part2() {
    __shared__ int s[256];
    int t = threadIdx.x;
    int v = (t < SCAN_BLOCKS) ? g_blksum[t] : 0;
    s[t] = v;
    __syncthreads();
    for (int o = 1; o < 256; o <<= 1) {
        int x = (t >= o) ? s[t - o] : 0;
        __syncthreads();
        s[t] += x;
        __syncthreads();
    }
    if (t < SCAN_BLOCKS) g_blkoff[t] = s[t] - v;
}

__global__ void scan_part3() {
    __shared__ int s[256];
    int t = threadIdx.x;
    int i = blockIdx.x * 256 + t;
    int v = (i < N_NODES) ? g_indeg[i] : 0;
    s[t] = v;
    __syncthreads();
    for (int o = 1; o < 256; o <<= 1) {
        int x = (t >= o) ? s[t - o] : 0;
        __syncthreads();
        s[t] += x;
        __syncthreads();
    }
    if (i < N_NODES) {
        int r = g_blkoff[blockIdx.x] + s[t] - v;
        g_rowptr[i] = r;
        if (i == N_NODES - 1) g_rowptr[N_NODES] = r + v;
    }
}

__global__ void fill_csr(const int* __restrict__ src, const int* __restrict__ dst) {
    int e = blockIdx.x * blockDim.x + threadIdx.x;
    if (e < N_EDGES) {
        int v = dst[e];
        int ofs = atomicAdd(&g_cursor[v], 1);
        g_csrsrc[g_rowptr[v] + ofs] = src[e];
    }
}

// ---------------- weight conversion: W [K][N] -> W^T [N][K] bf16 hi/lo ----------------
__global__ void wconvert(const float* W0, const float* W1, const float* W2,
                         const float* W3, const float* W4, const float* W5) {
    int idx = blockIdx.x * 256 + threadIdx.x;
    if (idx >= 6 * DIM * DIM) return;
    int layer = idx >> 14;
    int r = idx & 16383;
    int n = r >> 7, k = r & 127;
    const float* Ws[6] = {W0, W1, W2, W3, W4, W5};
    float val = Ws[layer][k * DIM + n];
    unsigned short hi, lo;
    split_bf(val, hi, lo);
    g_Whi[idx] = hi;   // layer*16384 + n*128 + k
    g_Wlo[idx] = lo;
}

// ---------------- aggregation: one warp per destination node, 4x unrolled ----------------
// OUT_BF16=1: write bf16 hi/lo row-major (GEMM input). Else fp32 to ext_out.
template <int SRC_NORM, int DST_NORM, int OUT_BF16>
__global__ void aggregate_kernel(const float* __restrict__ ext_in, int in_sel,
                                 float* __restrict__ ext_out) {
    const float* hin = (in_sel == 0) ? g_h[0] : (in_sel == 1) ? g_h[1] : ext_in;

    int v = (blockIdx.x * blockDim.x + threadIdx.x) >> 5;
    if (v >= N_NODES) return;
    int lane = threadIdx.x & 31;

    int beg = g_rowptr[v];
    int end = g_rowptr[v + 1];

    const float4* h4 = (const float4*)hin;
    float4 acc = make_float4(0.f, 0.f, 0.f, 0.f);

    int i = beg;
    for (; i + 4 <= end; i += 4) {
        int s0 = g_csrsrc[i + 0];
        int s1 = g_csrsrc[i + 1];
        int s2 = g_csrsrc[i + 2];
        int s3 = g_csrsrc[i + 3];
        float w0 = SRC_NORM ? g_ns[s0] : 1.0f;
        float w1 = SRC_NORM ? g_ns[s1] : 1.0f;
        float w2 = SRC_NORM ? g_ns[s2] : 1.0f;
        float w3 = SRC_NORM ? g_ns[s3] : 1.0f;
        float4 v0 = h4[s0 * 32 + lane];
        float4 v1 = h4[s1 * 32 + lane];
        float4 v2 = h4[s2 * 32 + lane];
        float4 v3 = h4[s3 * 32 + lane];
        acc.x += w0 * v0.x; acc.y += w0 * v0.y; acc.z += w0 * v0.z; acc.w += w0 * v0.w;
        acc.x += w1 * v1.x; acc.y += w1 * v1.y; acc.z += w1 * v1.z; acc.w += w1 * v1.w;
        acc.x += w2 * v2.x; acc.y += w2 * v2.y; acc.z += w2 * v2.z; acc.w += w2 * v2.w;
        acc.x += w3 * v3.x; acc.y += w3 * v3.y; acc.z += w3 * v3.z; acc.w += w3 * v3.w;
    }
    for (; i < end; i++) {
        int s = g_csrsrc[i];
        float w = SRC_NORM ? g_ns[s] : 1.0f;
        float4 vv = h4[s * 32 + lane];
        acc.x += w * vv.x; acc.y += w * vv.y; acc.z += w * vv.z; acc.w += w * vv.w;
    }
    if (DST_NORM) {
        float sc = g_nd[v];
        acc.x *= sc; acc.y *= sc; acc.z *= sc; acc.w *= sc;
    }

    if (OUT_BF16) {
        unsigned short h0, h1, h2, h3, l0, l1, l2, l3;
        split_bf(acc.x, h0, l0); split_bf(acc.y, h1, l1);
        split_bf(acc.z, h2, l2); split_bf(acc.w, h3, l3);
        uint2 hv = make_uint2((uint32_t)h0 | ((uint32_t)h1 << 16),
                              (uint32_t)h2 | ((uint32_t)h3 << 16));
        uint2 lv = make_uint2((uint32_t)l0 | ((uint32_t)l1 << 16),
                              (uint32_t)l2 | ((uint32_t)l3 << 16));
        *(uint2*)&g_Ahi[(size_t)v * DIM + lane * 4] = hv;
        *(uint2*)&g_Alo[(size_t)v * DIM + lane * 4] = lv;
    } else {
        ((float4*)ext_out)[v * 32 + lane] = acc;
    }
}

// ---------------- tensor-core GEMM via mma.sync (bf16x2 split, FUSED passes) ----------------
// g_h[out_buf][row] = relu(A[row] @ W + b) * (do_ps ? g_ns[row] : 1)
// CTA: 128 rows x 128 cols, 8 warps (4M x 2N), warp tile 32x64.
// Fragments for hi AND lo loaded once per k-step; all 3 products accumulate together.
__global__ void __launch_bounds__(256, 1) gemm_mma(
    const float* __restrict__ b, int layer, int out_buf, int do_ps) {
    extern __shared__ __align__(16) unsigned short sm[];
    unsigned short* sAh = sm;
    unsigned short* sAl = sm + 128 * SA;
    unsigned short* sWh = sm + 2 * 128 * SA;
    unsigned short* sWl = sm + 3 * 128 * SA;

    int tid = threadIdx.x;
    const uint4* gAh = (const uint4*)(g_Ahi + (size_t)blockIdx.x * (128 * DIM));
    const uint4* gAl = (const uint4*)(g_Alo + (size_t)blockIdx.x * (128 * DIM));
    const uint4* gWh = (const uint4*)(g_Whi + (size_t)layer * (DIM * DIM));
    const uint4* gWl = (const uint4*)(g_Wlo + (size_t)layer * (DIM * DIM));

    // stage tiles: 2048 uint4 each (128 rows x 16 uint4), padded smem stride
#pragma unroll
    for (int it = 0; it < 8; it++) {
        int i = tid + it * 256;
        int r = i >> 4, c = (i & 15) << 3;
        *(uint4*)&sAh[r * SA + c] = gAh[i];
        *(uint4*)&sAl[r * SA + c] = gAl[i];
        *(uint4*)&sWh[r * SA + c] = gWh[i];
        *(uint4*)&sWl[r * SA + c] = gWl[i];
    }
    __syncthreads();

    int warp = tid >> 5, lane = tid & 31;
    int wm = warp & 3, wn = warp >> 2;           // 4 M-warps x 2 N-warps
    int bm = wm * 32, bn = wn * 64;
    int lr = lane >> 2, lc = (lane & 3) * 2;

    float acc[2][8][4];
#pragma unroll
    for (int mi = 0; mi < 2; mi++)
#pragma unroll
        for (int ni = 0; ni < 8; ni++)
#pragma unroll
            for (int q = 0; q < 4; q++) acc[mi][ni][q] = 0.f;

#pragma unroll
    for (int k = 0; k < 8; k++) {
        int k0 = k * 16;
        uint32_t afh[2][4], afl[2][4], bfh[8][2], bfl[8][2];
#pragma unroll
        for (int mi = 0; mi < 2; mi++) {
            int r = bm + mi * 16 + lr;
            afh[mi][0] = *(const uint32_t*)&sAh[r * SA + k0 + lc];
            afh[mi][1] = *(const uint32_t*)&sAh[(r + 8) * SA + k0 + lc];
            afh[mi][2] = *(const uint32_t*)&sAh[r * SA + k0 + 8 + lc];
            afh[mi][3] = *(const uint32_t*)&sAh[(r + 8) * SA + k0 + 8 + lc];
            afl[mi][0] = *(const uint32_t*)&sAl[r * SA + k0 + lc];
            afl[mi][1] = *(const uint32_t*)&sAl[(r + 8) * SA + k0 + lc];
            afl[mi][2] = *(const uint32_t*)&sAl[r * SA + k0 + 8 + lc];
            afl[mi][3] = *(const uint32_t*)&sAl[(r + 8) * SA + k0 + 8 + lc];
        }
#pragma unroll
        for (int ni = 0; ni < 8; ni++) {
            int cc = bn + ni * 8 + lr;
            bfh[ni][0] = *(const uint32_t*)&sWh[cc * SA + k0 + lc];
            bfh[ni][1] = *(const uint32_t*)&sWh[cc * SA + k0 + 8 + lc];
            bfl[ni][0] = *(const uint32_t*)&sWl[cc * SA + k0 + lc];
            bfl[ni][1] = *(const uint32_t*)&sWl[cc * SA + k0 + 8 + lc];
        }
#pragma unroll
        for (int mi = 0; mi < 2; mi++)
#pragma unroll
            for (int ni = 0; ni < 8; ni++) {
                mma16816(acc[mi][ni], afh[mi], bfh[ni]);   // hi*hi
                mma16816(acc[mi][ni], afh[mi], bfl[ni]);   // hi*lo
                mma16816(acc[mi][ni], afl[mi], bfh[ni]);   // lo*hi
            }
    }

    float* C = g_h[out_buf];
#pragma unroll
    for (int mi = 0; mi < 2; mi++) {
        int r0 = blockIdx.x * 128 + bm + mi * 16 + lr;
        int r1 = r0 + 8;
        float ps0 = 1.f, ps1 = 1.f;
        if (do_ps) {
            if (r0 < N_NODES) ps0 = g_ns[r0];
            if (r1 < N_NODES) ps1 = g_ns[r1];
        }
#pragma unroll
        for (int ni = 0; ni < 8; ni++) {
            int col = bn + ni * 8 + lc;
            float2 bv = *(const float2*)&b[col];
            if (r0 < N_NODES) {
                float2 o;
                o.x = fmaxf(acc[mi][ni][0] + bv.x, 0.f) * ps0;
                o.y = fmaxf(acc[mi][ni][1] + bv.y, 0.f) * ps0;
                *(float2*)&C[(size_t)r0 * DIM + col] = o;
            }
            if (r1 < N_NODES) {
                float2 o;
                o.x = fmaxf(acc[mi][ni][2] + bv.x, 0.f) * ps1;
                o.y = fmaxf(acc[mi][ni][3] + bv.y, 0.f) * ps1;
                *(float2*)&C[(size_t)r1 * DIM + col] = o;
            }
        }
    }
}

// ---------------- pooling: sorted graph_id -> register accumulation ----------------
__global__ void pool_kernel(int buf, const int* __restrict__ gid) {
    const float* h = g_h[buf];
    int group = blockIdx.x * 2 + (threadIdx.x >> 7);
    int d = threadIdx.x & 127;
    int start = group * 128;
    if (start >= N_NODES) return;
    int end = min(start + 128, N_NODES);

    int cur = gid[start];
    float acc = 0.f;
    int cnt = 0;
    for (int n = start; n < end; n++) {
        int g = gid[n];
        if (g != cur) {
            atomicAdd(&g_pooled[cur * DIM + d], acc);
            if (d == 0) atomicAdd(&g_gcount[cur], cnt);
            acc = 0.f; cnt = 0; cur = g;
        }
        acc += h[n * DIM + d];
        cnt++;
    }
    atomicAdd(&g_pooled[cur * DIM + d], acc);
    if (d == 0) atomicAdd(&g_gcount[cur], cnt);
}

// ---------------- head MLP ----------------
__global__ void mlp_kernel(const float* __restrict__ Wa, const float* __restrict__ ba,
                           const float* __restrict__ Wb, const float* __restrict__ bb,
                           float* __restrict__ out) {
    __shared__ float pm[N_GRAPHS * DIM];
    __shared__ float z[N_GRAPHS * HID];
    int t = threadIdx.x;

    for (int i = t; i < N_GRAPHS * DIM; i += 256) {
        int g = i / DIM;
        float cnt = fmaxf((float)g_gcount[g], 1.0f);
        pm[i] = g_pooled[i] / cnt;
    }
    __syncthreads();

    for (int i = t; i < N_GRAPHS * HID; i += 256) {
        int g = i / HID, j = i % HID;
        float s = ba[j];
        for (int d = 0; d < DIM; d++) s += pm[g * DIM + d] * Wa[d * HID + j];
        z[i] = fmaxf(s, 0.0f);
    }
    __syncthreads();

    for (int i = t; i < N_GRAPHS * N_CLASS; i += 256) {
        int g = i / N_CLASS, c = i % N_CLASS;
        float s = bb[c];
        for (int j = 0; j < HID; j++) s += z[g * HID + j] * Wb[j * N_CLASS + c];
        out[i] = s;
    }
}

// ---------------- launch ----------------
extern "C" void kernel_launch(void* const* d_in, const int* in_sizes, int n_in,
                              void* d_out, int out_size) {
    const float* feat = (const float*)d_in[0];
    const int* src = (const int*)d_in[1];
    const int* dst = (const int*)d_in[2];
    const int* gid = (const int*)d_in[3];
    const float* Ws[6] = {(const float*)d_in[4], (const float*)d_in[6], (const float*)d_in[8],
                          (const float*)d_in[10], (const float*)d_in[12], (const float*)d_in[14]};
    const float* bs[6] = {(const float*)d_in[5], (const float*)d_in[7], (const float*)d_in[9],
                          (const float*)d_in[11], (const float*)d_in[13], (const float*)d_in[15]};
    const float* Wa = (const float*)d_in[16];
    const float* ba = (const float*)d_in[17];
    const float* Wb = (const float*)d_in[18];
    const float* bb = (const float*)d_in[19];
    float* out = (float*)d_out;

    const int SMEM_DYN = 4 * 128 * SA * 2;   // 139264 B
    cudaFuncSetAttribute(gemm_mma, cudaFuncAttributeMaxDynamicSharedMemorySize, SMEM_DYN);

    // graph structure
    zero_kernel<<<SCAN_BLOCKS, 256>>>();
    degree_kernel<<<(N_EDGES + 255) / 256, 256>>>(src, dst);
    norm_kernel<<<SCAN_BLOCKS, 256>>>();
    scan_part1<<<SCAN_BLOCKS, 256>>>();
    scan_part2<<<1, 256>>>();
    scan_part3<<<SCAN_BLOCKS, 256>>>();
    fill_csr<<<(N_EDGES + 255) / 256, 256>>>(src, dst);
    wconvert<<<(6 * DIM * DIM + 255) / 256, 256>>>(Ws[0], Ws[1], Ws[2], Ws[3], Ws[4], Ws[5]);

    const int AGG_GRID = (N_NODES * 32 + 255) / 256;

    // Layer 0: per-edge src norm. GEMM epilogue pre-scales layers 0..4 by ns,
    // so layers 1..5 aggregate without per-edge norm loads. relu(x)*ns == relu(x*ns).
    aggregate_kernel<1, 1, 1><<<AGG_GRID, 256>>>(feat, -1, nullptr);
    gemm_mma<<<N_TILES, 256, SMEM_DYN>>>(bs[0], 0, 0, 1);

    for (int L = 1; L < 6; L++) {
        aggregate_kernel<0, 1, 1><<<AGG_GRID, 256>>>(nullptr, (L - 1) & 1, nullptr);
        gemm_mma<<<N_TILES, 256, SMEM_DYN>>>(bs[L], L, L & 1, (L < 5) ? 1 : 0);
    }
    // final features in g_h[1]

    pool_kernel<<<SCAN_BLOCKS, 256>>>(1, gid);
    mlp_kernel<<<1, 256>>>(Wa, ba, Wb, bb, out);

    // unnormalized aggregation h_agg [50000,128] (fp32 exact)
    aggregate_kernel<0, 0, 0><<<AGG_GRID, 256>>>(nullptr, 1, out + N_GRAPHS * N_CLASS);
}

// round 9
// speedup vs baseline: 1.3877x; 1.0081x over previous
#include <cuda_runtime.h>
#include <cuda_bf16.h>
#include <cstdint>

#define N_NODES 50000
#define N_EDGES 800000
#define DIM     128
#define N_GRAPHS 64
#define N_CLASS  10
#define HID      64
#define SCAN_BLOCKS 196   // ceil(50000/256)
#define N_TILES 391       // ceil(50000/128)
#define N_PAD   (N_TILES * 128)
#define SA      136       // padded K-stride in smem (bank-conflict-free fragments)

// ---------------- device scratch ----------------
__device__ float g_h[2][N_NODES * DIM];
__device__ unsigned short g_Ahi[N_PAD * DIM];   // row-major bf16 hi of aggregated feats
__device__ unsigned short g_Alo[N_PAD * DIM];   // row-major bf16 lo
__device__ unsigned short g_Whi[6 * DIM * DIM]; // row-major W^T [N][K] bf16 hi
__device__ unsigned short g_Wlo[6 * DIM * DIM];
__device__ float g_ns[N_NODES];
__device__ float g_nd[N_NODES];
__device__ int   g_indeg[N_NODES];
__device__ int   g_outdeg[N_NODES];
__device__ int   g_rowptr[N_NODES + 1];
__device__ int   g_cursor[N_NODES];
__device__ int   g_csrsrc[N_EDGES];
__device__ float g_pooled[N_GRAPHS * DIM];
__device__ int   g_gcount[N_GRAPHS];

__device__ __forceinline__ void split_bf(float x, unsigned short& hi, unsigned short& lo) {
    __nv_bfloat16 h = __float2bfloat16_rn(x);
    hi = __bfloat16_as_ushort(h);
    lo = __bfloat16_as_ushort(__float2bfloat16_rn(x - __bfloat162float(h)));
}

__device__ __forceinline__ void mma16816(float* c, const uint32_t* a, const uint32_t* b) {
    asm volatile(
        "mma.sync.aligned.m16n8k16.row.col.f32.bf16.bf16.f32 "
        "{%0,%1,%2,%3}, {%4,%5,%6,%7}, {%8,%9}, {%0,%1,%2,%3};"
        : "+f"(c[0]), "+f"(c[1]), "+f"(c[2]), "+f"(c[3])
        : "r"(a[0]), "r"(a[1]), "r"(a[2]), "r"(a[3]), "r"(b[0]), "r"(b[1]));
}

// ---------------- setup: zero counters + tail tiles + weight conversion (one launch) ----------------
// grid = 384 blocks x 256 = 98304 threads (= 6*128*128 weight elements)
__global__ void setup_kernel(const float* W0, const float* W1, const float* W2,
                             const float* W3, const float* W4, const float* W5) {
    int idx = blockIdx.x * 256 + threadIdx.x;
    if (idx < N_NODES) { g_indeg[idx] = 0; g_outdeg[idx] = 0; g_cursor[idx] = 0; }
    if (idx < N_GRAPHS * DIM) g_pooled[idx] = 0.0f;
    if (idx < N_GRAPHS) g_gcount[idx] = 0;
    // zero padded tail rows (50000..50047) once; they never get written again
    if (idx < 768) ((uint4*)(g_Ahi + N_NODES * DIM))[idx] = make_uint4(0, 0, 0, 0);
    else if (idx < 1536) ((uint4*)(g_Alo + N_NODES * DIM))[idx - 768] = make_uint4(0, 0, 0, 0);

    // weight conversion: W [K][N] -> W^T [N][K] bf16 hi/lo
    int layer = idx >> 14;
    int r = idx & 16383;
    int n = r >> 7, k = r & 127;
    const float* Ws[6] = {W0, W1, W2, W3, W4, W5};
    float val = Ws[layer][k * DIM + n];
    unsigned short hi, lo;
    split_bf(val, hi, lo);
    g_Whi[idx] = hi;
    g_Wlo[idx] = lo;
}

__global__ void degree_kernel(const int* __restrict__ src, const int* __restrict__ dst) {
    int e = blockIdx.x * blockDim.x + threadIdx.x;
    if (e < N_EDGES) {
        atomicAdd(&g_outdeg[src[e]], 1);
        atomicAdd(&g_indeg[dst[e]], 1);
    }
}

// ---------------- norm + full exclusive scan of indeg -> rowptr, ONE launch ----------------
// Each block computes its global offset by directly summing indeg[0..blockStart).
__global__ void scanfull_kernel() {
    __shared__ int ws[8];
    __shared__ int s[256];
    __shared__ int boff_sh;
    int t = threadIdx.x;
    int base = blockIdx.x * 256;
    int i = base + t;

    if (i < N_NODES) {
        g_ns[i] = rsqrtf((float)max(g_outdeg[i], 1));
        g_nd[i] = rsqrtf((float)max(g_indeg[i], 1));
    }

    // partial sum of all indeg before this block
    int part = 0;
    for (int j = t; j < base; j += 256) part += g_indeg[j];
#pragma unroll
    for (int o = 16; o; o >>= 1) part += __shfl_down_sync(0xffffffffu, part, o);
    if ((t & 31) == 0) ws[t >> 5] = part;

    int v = (i < N_NODES) ? g_indeg[i] : 0;
    s[t] = v;
    __syncthreads();
    if (t == 0) {
        int b = 0;
#pragma unroll
        for (int w = 0; w < 8; w++) b += ws[w];
        boff_sh = b;
    }
    __syncthreads();
    int boff = boff_sh;

    // local inclusive scan (Hillis-Steele)
    for (int o = 1; o < 256; o <<= 1) {
        int x = (t >= o) ? s[t - o] : 0;
        __syncthreads();
        s[t] += x;
        __syncthreads();
    }
    if (i < N_NODES) {
        int r = boff + s[t] - v;
        g_rowptr[i] = r;
        if (i == N_NODES - 1) g_rowptr[N_NODES] = r + v;
    }
}

__global__ void fill_csr(const int* __restrict__ src, const int* __restrict__ dst) {
    int e = blockIdx.x * blockDim.x + threadIdx.x;
    if (e < N_EDGES) {
        int v = dst[e];
        int ofs = atomicAdd(&g_cursor[v], 1);
        g_csrsrc[g_rowptr[v] + ofs] = src[e];
    }
}

// ---------------- aggregation: one warp per destination node, 4x unrolled ----------------
// OUT_BF16=1: write bf16 hi/lo row-major (GEMM input). Else fp32 to ext_out.
template <int SRC_NORM, int DST_NORM, int OUT_BF16>
__global__ void aggregate_kernel(const float* __restrict__ ext_in, int in_sel,
                                 float* __restrict__ ext_out) {
    const float* hin = (in_sel == 0) ? g_h[0] : (in_sel == 1) ? g_h[1] : ext_in;

    int v = (blockIdx.x * blockDim.x + threadIdx.x) >> 5;
    if (v >= N_NODES) return;
    int lane = threadIdx.x & 31;

    int beg = g_rowptr[v];
    int end = g_rowptr[v + 1];

    const float4* h4 = (const float4*)hin;
    float4 acc = make_float4(0.f, 0.f, 0.f, 0.f);

    int i = beg;
    for (; i + 4 <= end; i += 4) {
        int s0 = g_csrsrc[i + 0];
        int s1 = g_csrsrc[i + 1];
        int s2 = g_csrsrc[i + 2];
        int s3 = g_csrsrc[i + 3];
        float w0 = SRC_NORM ? g_ns[s0] : 1.0f;
        float w1 = SRC_NORM ? g_ns[s1] : 1.0f;
        float w2 = SRC_NORM ? g_ns[s2] : 1.0f;
        float w3 = SRC_NORM ? g_ns[s3] : 1.0f;
        float4 v0 = h4[s0 * 32 + lane];
        float4 v1 = h4[s1 * 32 + lane];
        float4 v2 = h4[s2 * 32 + lane];
        float4 v3 = h4[s3 * 32 + lane];
        acc.x += w0 * v0.x; acc.y += w0 * v0.y; acc.z += w0 * v0.z; acc.w += w0 * v0.w;
        acc.x += w1 * v1.x; acc.y += w1 * v1.y; acc.z += w1 * v1.z; acc.w += w1 * v1.w;
        acc.x += w2 * v2.x; acc.y += w2 * v2.y; acc.z += w2 * v2.z; acc.w += w2 * v2.w;
        acc.x += w3 * v3.x; acc.y += w3 * v3.y; acc.z += w3 * v3.z; acc.w += w3 * v3.w;
    }
    for (; i < end; i++) {
        int s = g_csrsrc[i];
        float w = SRC_NORM ? g_ns[s] : 1.0f;
        float4 vv = h4[s * 32 + lane];
        acc.x += w * vv.x; acc.y += w * vv.y; acc.z += w * vv.z; acc.w += w * vv.w;
    }
    if (DST_NORM) {
        float sc = g_nd[v];
        acc.x *= sc; acc.y *= sc; acc.z *= sc; acc.w *= sc;
    }

    if (OUT_BF16) {
        unsigned short h0, h1, h2, h3, l0, l1, l2, l3;
        split_bf(acc.x, h0, l0); split_bf(acc.y, h1, l1);
        split_bf(acc.z, h2, l2); split_bf(acc.w, h3, l3);
        uint2 hv = make_uint2((uint32_t)h0 | ((uint32_t)h1 << 16),
                              (uint32_t)h2 | ((uint32_t)h3 << 16));
        uint2 lv = make_uint2((uint32_t)l0 | ((uint32_t)l1 << 16),
                              (uint32_t)l2 | ((uint32_t)l3 << 16));
        *(uint2*)&g_Ahi[(size_t)v * DIM + lane * 4] = hv;
        *(uint2*)&g_Alo[(size_t)v * DIM + lane * 4] = lv;
    } else {
        ((float4*)ext_out)[v * 32 + lane] = acc;
    }
}

// ---------------- tensor-core GEMM via mma.sync (bf16x2 split, fused passes) ----------------
// g_h[out_buf][row] = relu(A[row] @ W + b) * (do_ps ? g_ns[row] : 1)
// CTA: 128 rows x 128 cols, 8 warps (4M x 2N), warp tile 32x64.
__global__ void __launch_bounds__(256, 1) gemm_mma(
    const float* __restrict__ b, int layer, int out_buf, int do_ps) {
    extern __shared__ __align__(16) unsigned short sm[];
    unsigned short* sAh = sm;
    unsigned short* sAl = sm + 128 * SA;
    unsigned short* sWh = sm + 2 * 128 * SA;
    unsigned short* sWl = sm + 3 * 128 * SA;

    int tid = threadIdx.x;
    const uint4* gAh = (const uint4*)(g_Ahi + (size_t)blockIdx.x * (128 * DIM));
    const uint4* gAl = (const uint4*)(g_Alo + (size_t)blockIdx.x * (128 * DIM));
    const uint4* gWh = (const uint4*)(g_Whi + (size_t)layer * (DIM * DIM));
    const uint4* gWl = (const uint4*)(g_Wlo + (size_t)layer * (DIM * DIM));

#pragma unroll
    for (int it = 0; it < 8; it++) {
        int i = tid + it * 256;
        int r = i >> 4, c = (i & 15) << 3;
        *(uint4*)&sAh[r * SA + c] = gAh[i];
        *(uint4*)&sAl[r * SA + c] = gAl[i];
        *(uint4*)&sWh[r * SA + c] = gWh[i];
        *(uint4*)&sWl[r * SA + c] = gWl[i];
    }
    __syncthreads();

    int warp = tid >> 5, lane = tid & 31;
    int wm = warp & 3, wn = warp >> 2;           // 4 M-warps x 2 N-warps
    int bm = wm * 32, bn = wn * 64;
    int lr = lane >> 2, lc = (lane & 3) * 2;

    float acc[2][8][4];
#pragma unroll
    for (int mi = 0; mi < 2; mi++)
#pragma unroll
        for (int ni = 0; ni < 8; ni++)
#pragma unroll
            for (int q = 0; q < 4; q++) acc[mi][ni][q] = 0.f;

#pragma unroll
    for (int k = 0; k < 8; k++) {
        int k0 = k * 16;
        uint32_t afh[2][4], afl[2][4], bfh[8][2], bfl[8][2];
#pragma unroll
        for (int mi = 0; mi < 2; mi++) {
            int r = bm + mi * 16 + lr;
            afh[mi][0] = *(const uint32_t*)&sAh[r * SA + k0 + lc];
            afh[mi][1] = *(const uint32_t*)&sAh[(r + 8) * SA + k0 + lc];
            afh[mi][2] = *(const uint32_t*)&sAh[r * SA + k0 + 8 + lc];
            afh[mi][3] = *(const uint32_t*)&sAh[(r + 8) * SA + k0 + 8 + lc];
            afl[mi][0] = *(const uint32_t*)&sAl[r * SA + k0 + lc];
            afl[mi][1] = *(const uint32_t*)&sAl[(r + 8) * SA + k0 + lc];
            afl[mi][2] = *(const uint32_t*)&sAl[r * SA + k0 + 8 + lc];
            afl[mi][3] = *(const uint32_t*)&sAl[(r + 8) * SA + k0 + 8 + lc];
        }
#pragma unroll
        for (int ni = 0; ni < 8; ni++) {
            int cc = bn + ni * 8 + lr;
            bfh[ni][0] = *(const uint32_t*)&sWh[cc * SA + k0 + lc];
            bfh[ni][1] = *(const uint32_t*)&sWh[cc * SA + k0 + 8 + lc];
            bfl[ni][0] = *(const uint32_t*)&sWl[cc * SA + k0 + lc];
            bfl[ni][1] = *(const uint32_t*)&sWl[cc * SA + k0 + 8 + lc];
        }
#pragma unroll
        for (int mi = 0; mi < 2; mi++)
#pragma unroll
            for (int ni = 0; ni < 8; ni++) {
                mma16816(acc[mi][ni], afh[mi], bfh[ni]);   // hi*hi
                mma16816(acc[mi][ni], afh[mi], bfl[ni]);   // hi*lo
                mma16816(acc[mi][ni], afl[mi], bfh[ni]);   // lo*hi
            }
    }

    float* C = g_h[out_buf];
#pragma unroll
    for (int mi = 0; mi < 2; mi++) {
        int r0 = blockIdx.x * 128 + bm + mi * 16 + lr;
        int r1 = r0 + 8;
        float ps0 = 1.f, ps1 = 1.f;
        if (do_ps) {
            if (r0 < N_NODES) ps0 = g_ns[r0];
            if (r1 < N_NODES) ps1 = g_ns[r1];
        }
#pragma unroll
        for (int ni = 0; ni < 8; ni++) {
            int col = bn + ni * 8 + lc;
            float2 bv = *(const float2*)&b[col];
            if (r0 < N_NODES) {
                float2 o;
                o.x = fmaxf(acc[mi][ni][0] + bv.x, 0.f) * ps0;
                o.y = fmaxf(acc[mi][ni][1] + bv.y, 0.f) * ps0;
                *(float2*)&C[(size_t)r0 * DIM + col] = o;
            }
            if (r1 < N_NODES) {
                float2 o;
                o.x = fmaxf(acc[mi][ni][2] + bv.x, 0.f) * ps1;
                o.y = fmaxf(acc[mi][ni][3] + bv.y, 0.f) * ps1;
                *(float2*)&C[(size_t)r1 * DIM + col] = o;
            }
        }
    }
}

// ---------------- pooling: sorted graph_id -> register accumulation ----------------
__global__ void pool_kernel(int buf, const int* __restrict__ gid) {
    const float* h = g_h[buf];
    int group = blockIdx.x * 2 + (threadIdx.x >> 7);
    int d = threadIdx.x & 127;
    int start = group * 128;
    if (start >= N_NODES) return;
    int end = min(start + 128, N_NODES);

    int cur = gid[start];
    float acc = 0.f;
    int cnt = 0;
    for (int n = start; n < end; n++) {
        int g = gid[n];
        if (g != cur) {
            atomicAdd(&g_pooled[cur * DIM + d], acc);
            if (d == 0) atomicAdd(&g_gcount[cur], cnt);
            acc = 0.f; cnt = 0; cur = g;
        }
        acc += h[n * DIM + d];
        cnt++;
    }
    atomicAdd(&g_pooled[cur * DIM + d], acc);
    if (d == 0) atomicAdd(&g_gcount[cur], cnt);
}

// ---------------- head MLP ----------------
__global__ void mlp_kernel(const float* __restrict__ Wa, const float* __restrict__ ba,
                           const float* __restrict__ Wb, const float* __restrict__ bb,
                           float* __restrict__ out) {
    __shared__ float pm[N_GRAPHS * DIM];
    __shared__ float z[N_GRAPHS * HID];
    int t = threadIdx.x;

    for (int i = t; i < N_GRAPHS * DIM; i += 256) {
        int g = i / DIM;
        float cnt = fmaxf((float)g_gcount[g], 1.0f);
        pm[i] = g_pooled[i] / cnt;
    }
    __syncthreads();

    for (int i = t; i < N_GRAPHS * HID; i += 256) {
        int g = i / HID, j = i % HID;
        float s = ba[j];
        for (int d = 0; d < DIM; d++) s += pm[g * DIM + d] * Wa[d * HID + j];
        z[i] = fmaxf(s, 0.0f);
    }
    __syncthreads();

    for (int i = t; i < N_GRAPHS * N_CLASS; i += 256) {
        int g = i / N_CLASS, c = i % N_CLASS;
        float s = bb[c];
        for (int j = 0; j < HID; j++) s += z[g * HID + j] * Wb[j * N_CLASS + c];
        out[i] = s;
    }
}

// ---------------- launch ----------------
extern "C" void kernel_launch(void* const* d_in, const int* in_sizes, int n_in,
                              void* d_out, int out_size) {
    const float* feat = (const float*)d_in[0];
    const int* src = (const int*)d_in[1];
    const int* dst = (const int*)d_in[2];
    const int* gid = (const int*)d_in[3];
    const float* Ws[6] = {(const float*)d_in[4], (const float*)d_in[6], (const float*)d_in[8],
                          (const float*)d_in[10], (const float*)d_in[12], (const float*)d_in[14]};
    const float* bs[6] = {(const float*)d_in[5], (const float*)d_in[7], (const float*)d_in[9],
                          (const float*)d_in[11], (const float*)d_in[13], (const float*)d_in[15]};
    const float* Wa = (const float*)d_in[16];
    const float* ba = (const float*)d_in[17];
    const float* Wb = (const float*)d_in[18];
    const float* bb = (const float*)d_in[19];
    float* out = (float*)d_out;

    const int SMEM_DYN = 4 * 128 * SA * 2;   // 139264 B
    cudaFuncSetAttribute(gemm_mma, cudaFuncAttributeMaxDynamicSharedMemorySize, SMEM_DYN);

    // graph structure: 4 launches (zero+wconvert merged; norm+scan merged)
    setup_kernel<<<384, 256>>>(Ws[0], Ws[1], Ws[2], Ws[3], Ws[4], Ws[5]);
    degree_kernel<<<(N_EDGES + 255) / 256, 256>>>(src, dst);
    scanfull_kernel<<<SCAN_BLOCKS, 256>>>();
    fill_csr<<<(N_EDGES + 255) / 256, 256>>>(src, dst);

    const int AGG_GRID = (N_NODES * 32 + 255) / 256;

    // Layer 0: per-edge src norm. GEMM epilogue pre-scales layers 0..4 by ns,
    // so layers 1..5 aggregate without per-edge norm loads. relu(x)*ns == relu(x*ns).
    aggregate_kernel<1, 1, 1><<<AGG_GRID, 256>>>(feat, -1, nullptr);
    gemm_mma<<<N_TILES, 256, SMEM_DYN>>>(bs[0], 0, 0, 1);

    for (int L = 1; L < 6; L++) {
        aggregate_kernel<0, 1, 1><<<AGG_GRID, 256>>>(nullptr, (L - 1) & 1, nullptr);
        gemm_mma<<<N_TILES, 256, SMEM_DYN>>>(bs[L], L, L & 1, (L < 5) ? 1 : 0);
    }
    // final features in g_h[1]

    pool_kernel<<<SCAN_BLOCKS, 256>>>(1, gid);
    mlp_kernel<<<1, 256>>>(Wa, ba, Wb, bb, out);

    // unnormalized aggregation h_agg [50000,128] (fp32 exact)
    aggregate_kernel<0, 0, 0><<<AGG_GRID, 256>>>(nullptr, 1, out + N_GRAPHS * N_CLASS);
}